// round 1
// baseline (speedup 1.0000x reference)
#include <cuda_runtime.h>

#define N_NODES 8192
#define DEGREE  32
#define N_EDGES (N_NODES * DEGREE)
#define D_FEAT  256
#define D4      (D_FEAT / 4)          // float4 columns per row
#define ROWS_PER_BLOCK 4
#define SPMM_THREADS   (ROWS_PER_BLOCK * D4)   // 256

// ---- device scratch (static; no allocation anywhere) ----
__device__ float  g_w[N_EDGES];                 // normalized edge weights
__device__ int    g_dst[N_EDGES];               // int32 gather indices
__device__ float4 g_x0[N_NODES * D4];           // ping
__device__ float4 g_x1[N_NODES * D4];           // pong
__device__ int    g_is64;                       // dst dtype flag

// ---------------------------------------------------------------------------
// Detect whether dst buffer holds int64 or int32 values.
// dst ~ U[0, 8192): if stored as little-endian int64, every odd 32-bit word
// is the (zero) high half. Probability of false positive for int32 data is
// (1/8192)^32 ~ 0.
// ---------------------------------------------------------------------------
__global__ void detect_kernel(const void* dst_raw) {
    const int* p = (const int*)dst_raw;
    int all_zero = 1;
    for (int k = 1; k < 64; k += 2) {
        if (p[k] != 0) all_zero = 0;
    }
    g_is64 = all_zero;
}

// ---------------------------------------------------------------------------
// Per-row weight normalization + dst decode. One warp per node row
// (DEGREE == 32 lanes). src is structurally repeat(arange(N_NODES), DEGREE)
// per the problem setup, so edge j belongs to row j / DEGREE.
// Duplicate (src,dst) pairs accumulate linearly in the weighted sum, which
// exactly matches COO .add + row-normalization semantics.
// ---------------------------------------------------------------------------
__global__ void prep_kernel(const void* dst_raw, const float* __restrict__ e) {
    int warp = (blockIdx.x * blockDim.x + threadIdx.x) >> 5;
    int lane = threadIdx.x & 31;
    if (warp >= N_NODES) return;
    int j = warp * DEGREE + lane;

    float ev = e[j];
    float s  = ev;
    #pragma unroll
    for (int o = 16; o > 0; o >>= 1) s += __shfl_xor_sync(0xffffffffu, s, o);
    g_w[j] = ev / s;

    int d;
    if (g_is64) d = (int)((const long long*)dst_raw)[j];
    else        d = ((const int*)dst_raw)[j];
    g_dst[j] = d;
}

// ---------------------------------------------------------------------------
// One diffusion step: xout[r] = sum_k w[r,k] * xin[dst[r,k]]
// Optionally accumulate scale * xout into out (the final answer).
//
// Buffer selection is done in-kernel from the iteration parity so the host
// never needs cudaGetSymbolAddress during graph capture.
//   iter t (1-based): input  = (t==1) ? h_ext : buffer[(t-1)&1]
//                     output = buffer[t&1]
// ---------------------------------------------------------------------------
__global__ void __launch_bounds__(SPMM_THREADS)
spmm_kernel(const float4* __restrict__ xin_ext, int use_ext, int t,
            float4* __restrict__ out, float scale, int init_out) {
    __shared__ float s_w[ROWS_PER_BLOCK][DEGREE];
    __shared__ int   s_d[ROWS_PER_BLOCK][DEGREE];

    const float4* __restrict__ xin =
        use_ext ? xin_ext : (((t - 1) & 1) ? g_x1 : g_x0);
    float4* __restrict__ xout = (t & 1) ? g_x1 : g_x0;

    int tid = threadIdx.x;
    int r   = tid >> 6;        // row within block (0..3)
    int c   = tid & 63;        // float4 column (0..63)
    int row = blockIdx.x * ROWS_PER_BLOCK + r;

    if (c < DEGREE) {
        int j = row * DEGREE + c;
        s_w[r][c] = g_w[j];
        s_d[r][c] = g_dst[j] * D4;
    }
    __syncthreads();

    float4 acc = make_float4(0.f, 0.f, 0.f, 0.f);
    #pragma unroll 8
    for (int k = 0; k < DEGREE; k++) {
        float  w = s_w[r][k];
        float4 v = xin[s_d[r][k] + c];
        acc.x += w * v.x;
        acc.y += w * v.y;
        acc.z += w * v.z;
        acc.w += w * v.w;
    }

    int oidx = row * D4 + c;
    xout[oidx] = acc;

    if (scale != 0.0f) {
        float4 o;
        if (init_out) o = make_float4(0.f, 0.f, 0.f, 0.f);
        else          o = out[oidx];
        o.x += scale * acc.x;
        o.y += scale * acc.y;
        o.z += scale * acc.z;
        o.w += scale * acc.w;
        out[oidx] = o;
    }
}

// ---------------------------------------------------------------------------
// inputs (metadata order): src(int), dst(int), e(float32), h(float32)
// output: float32 [N_NODES, D_FEAT]
// ---------------------------------------------------------------------------
extern "C" void kernel_launch(void* const* d_in, const int* in_sizes, int n_in,
                              void* d_out, int out_size) {
    const void*   dst = d_in[1];
    const float*  e   = (const float*)d_in[2];
    const float4* h   = (const float4*)d_in[3];
    float4*       out = (float4*)d_out;

    detect_kernel<<<1, 1>>>(dst);
    prep_kernel<<<N_NODES * DEGREE / 256, 256>>>(dst, e);

    // out = A h + (A^2 h)/1! + (A^4 h)/2! + (A^8 h)/3! + (A^16 h)/4! + (A^32 h)/5!
    const int grid = N_NODES / ROWS_PER_BLOCK;
    for (int t = 1; t <= 32; t++) {
        float scale = 0.0f;
        switch (t) {
            case 1:  scale = 1.0f;          break;
            case 2:  scale = 1.0f;          break;
            case 4:  scale = 1.0f / 2.0f;   break;
            case 8:  scale = 1.0f / 6.0f;   break;
            case 16: scale = 1.0f / 24.0f;  break;
            case 32: scale = 1.0f / 120.0f; break;
            default: break;
        }
        spmm_kernel<<<grid, SPMM_THREADS>>>(h, t == 1 ? 1 : 0, t,
                                            out, scale, t == 1 ? 1 : 0);
    }
}

// round 2
// speedup vs baseline: 1.0249x; 1.0249x over previous
#include <cuda_runtime.h>

#define N_NODES 8192
#define DEGREE  32
#define N_EDGES (N_NODES * DEGREE)
#define D_FEAT  256
#define D4      (D_FEAT / 4)            // 64 float4 columns per row
#define ROWS_PER_BLOCK 4
#define SPMM_THREADS   (ROWS_PER_BLOCK * D4)   // 256

// ---- device scratch (static; no allocation anywhere) ----
__device__ int2   g_wd[N_EDGES];        // {dst * D4, weight bits}
__device__ float4 g_x0[N_NODES * D4];   // ping
__device__ float4 g_x1[N_NODES * D4];   // pong

// ---------------------------------------------------------------------------
// Prep: per-row weight normalization + dst decode, packed into int2.
// One warp per node row (DEGREE == 32 lanes). src is structurally
// repeat(arange(N_NODES), DEGREE) per the problem setup, so edge j belongs to
// row j / DEGREE. Duplicate (src,dst) pairs accumulate linearly in the
// weighted sum, matching COO .add + row-normalization semantics.
//
// int64-vs-int32 dst detection is done locally per thread: dst values are in
// [0, 8192), so if stored as little-endian int64 every odd 32-bit word of the
// first 64 words is zero. All loads hit the same two L1 lines (broadcast).
// ---------------------------------------------------------------------------
__global__ void prep_kernel(const void* __restrict__ dst_raw,
                            const float* __restrict__ e) {
    const int* p = (const int*)dst_raw;
    int is64 = 1;
    #pragma unroll
    for (int k = 1; k < 64; k += 2) is64 &= (p[k] == 0);

    int warp = (blockIdx.x * blockDim.x + threadIdx.x) >> 5;
    int lane = threadIdx.x & 31;
    if (warp >= N_NODES) return;
    int j = warp * DEGREE + lane;

    float ev = e[j];
    float s  = ev;
    #pragma unroll
    for (int o = 16; o > 0; o >>= 1) s += __shfl_xor_sync(0xffffffffu, s, o);

    int d;
    if (is64) d = (int)((const long long*)dst_raw)[j];
    else      d = ((const int*)dst_raw)[j];

    g_wd[j] = make_int2(d * D4, __float_as_int(ev / s));
}

// ---------------------------------------------------------------------------
// One diffusion step: xout[r] = sum_k w[r,k] * xin[dst[r,k]]
// 4 rows per CTA, 64 threads per row (one float4 column each).
// Inner loop explicitly batches 8 independent float4 gathers into registers
// to expose MLP=8 per thread (covers L2 latency with 4 CTAs/SM resident).
//
// Buffer parity chosen in-kernel: iter t (1-based):
//   input  = (t==1) ? h : buffer[(t-1)&1],  output = buffer[t&1]
// ---------------------------------------------------------------------------
__global__ void __launch_bounds__(SPMM_THREADS, 4)
spmm_kernel(const float4* __restrict__ xin_ext, int t,
            float4* __restrict__ out, float scale) {
    __shared__ int2 s_wd[ROWS_PER_BLOCK][DEGREE];

    const float4* __restrict__ xin =
        (t == 1) ? xin_ext : (((t - 1) & 1) ? g_x1 : g_x0);
    float4* __restrict__ xout = (t & 1) ? g_x1 : g_x0;

    int tid = threadIdx.x;
    int r   = tid >> 6;        // row within block (0..3)
    int c   = tid & 63;        // float4 column (0..63)
    int row = blockIdx.x * ROWS_PER_BLOCK + r;

    if (tid < ROWS_PER_BLOCK * DEGREE) {
        int rr = tid >> 5, kk = tid & 31;
        s_wd[rr][kk] = g_wd[(blockIdx.x * ROWS_PER_BLOCK + rr) * DEGREE + kk];
    }
    __syncthreads();

    const float4* __restrict__ pin = xin + c;

    float4 acc = make_float4(0.f, 0.f, 0.f, 0.f);
    #pragma unroll
    for (int k = 0; k < DEGREE; k += 8) {
        int2 wd[8];
        #pragma unroll
        for (int u = 0; u < 8; u++) wd[u] = s_wd[r][k + u];
        float4 v[8];
        #pragma unroll
        for (int u = 0; u < 8; u++) v[u] = pin[wd[u].x];
        #pragma unroll
        for (int u = 0; u < 8; u++) {
            float w = __int_as_float(wd[u].y);
            acc.x += w * v[u].x;
            acc.y += w * v[u].y;
            acc.z += w * v[u].z;
            acc.w += w * v[u].w;
        }
    }

    int oidx = row * D4 + c;
    if (t != 32) xout[oidx] = acc;      // last iteration only feeds `out`

    if (scale != 0.0f) {
        float4 o;
        if (t == 1) o = make_float4(0.f, 0.f, 0.f, 0.f);
        else        o = out[oidx];
        o.x += scale * acc.x;
        o.y += scale * acc.y;
        o.z += scale * acc.z;
        o.w += scale * acc.w;
        out[oidx] = o;
    }
}

// ---------------------------------------------------------------------------
// inputs (metadata order): src(int), dst(int), e(float32), h(float32)
// output: float32 [N_NODES, D_FEAT]
//
// out = A h + (A^2 h)/1! + (A^4 h)/2! + (A^8 h)/3! + (A^16 h)/4! + (A^32 h)/5!
// computed as 32 sparse applications with tap accumulation at
// t in {1, 2, 4, 8, 16, 32}.
// ---------------------------------------------------------------------------
extern "C" void kernel_launch(void* const* d_in, const int* in_sizes, int n_in,
                              void* d_out, int out_size) {
    const void*   dst = d_in[1];
    const float*  e   = (const float*)d_in[2];
    const float4* h   = (const float4*)d_in[3];
    float4*       out = (float4*)d_out;

    prep_kernel<<<N_EDGES / 256, 256>>>(dst, e);

    const int grid = N_NODES / ROWS_PER_BLOCK;
    for (int t = 1; t <= 32; t++) {
        float scale = 0.0f;
        switch (t) {
            case 1:  scale = 1.0f;          break;
            case 2:  scale = 1.0f;          break;
            case 4:  scale = 1.0f / 2.0f;   break;
            case 8:  scale = 1.0f / 6.0f;   break;
            case 16: scale = 1.0f / 24.0f;  break;
            case 32: scale = 1.0f / 120.0f; break;
            default: break;
        }
        spmm_kernel<<<grid, SPMM_THREADS>>>(h, t, out, scale);
    }
}

// round 3
// speedup vs baseline: 1.4007x; 1.3667x over previous
#include <cuda_runtime.h>
#include <cuda_bf16.h>

#define N_NODES 8192
#define DEGREE  32
#define N_EDGES (N_NODES * DEGREE)
#define D_FEAT  256
#define D4      (D_FEAT / 4)            // 64 float4 columns per fp32 row
#define G16     (D_FEAT / 8)            // 32 16B granules per bf16 row

// ---- device scratch (static; no allocation anywhere) ----
__device__ int2   g_wd[N_EDGES];          // {dst, weight bits}
__device__ float4 g_x0[N_NODES * D4];     // fp32 buffer (t=1 output)
__device__ uint4  g_b0[N_NODES * G16];    // bf16 ping
__device__ uint4  g_b1[N_NODES * G16];    // bf16 pong

// ---------------------------------------------------------------------------
// Prep: per-row weight normalization + dst decode, packed into int2 {dst, w}.
// One warp per node row (DEGREE == 32 lanes). src is structurally
// repeat(arange(N_NODES), DEGREE), so edge j belongs to row j / DEGREE.
// Duplicate (src,dst) pairs accumulate linearly in the weighted sum, matching
// COO .add + row-normalization semantics.
// int64-vs-int32 dst detection: dst in [0,8192), so little-endian int64
// storage means every odd 32-bit word of the first 64 words is zero.
// ---------------------------------------------------------------------------
__global__ void prep_kernel(const void* __restrict__ dst_raw,
                            const float* __restrict__ e) {
    const int* p = (const int*)dst_raw;
    int is64 = 1;
    #pragma unroll
    for (int k = 1; k < 64; k += 2) is64 &= (p[k] == 0);

    int warp = (blockIdx.x * blockDim.x + threadIdx.x) >> 5;
    int lane = threadIdx.x & 31;
    if (warp >= N_NODES) return;
    int j = warp * DEGREE + lane;

    float ev = e[j];
    float s  = ev;
    #pragma unroll
    for (int o = 16; o > 0; o >>= 1) s += __shfl_xor_sync(0xffffffffu, s, o);

    int d;
    if (is64) d = (int)((const long long*)dst_raw)[j];
    else      d = ((const int*)dst_raw)[j];

    g_wd[j] = make_int2(d, __float_as_int(ev / s));
}

// ---------------------------------------------------------------------------
// fp32 step (t=1,2): xout[r] = sum_k w[r,k] * xin[dst[r,k]]
//   t=1: in = h (ext), out = g_x0 fp32, tap 1.0 (init d_out)
//   t=2: in = g_x0,    out = g_b0 bf16, tap 1.0
// 4 rows/CTA, 64 threads/row, float4 gathers, MLP=8.
// ---------------------------------------------------------------------------
__global__ void __launch_bounds__(256, 4)
spmm_f32(const float4* __restrict__ xin_ext, int t, float4* __restrict__ out) {
    __shared__ int2 s_wd[4][DEGREE];

    const float4* __restrict__ xin = (t == 1) ? xin_ext : g_x0;

    int tid = threadIdx.x;
    int r   = tid >> 6;        // row within block (0..3)
    int c   = tid & 63;        // float4 column (0..63)
    int row = blockIdx.x * 4 + r;

    if (tid < 4 * DEGREE) {
        int rr = tid >> 5, kk = tid & 31;
        s_wd[rr][kk] = g_wd[(blockIdx.x * 4 + rr) * DEGREE + kk];
    }
    __syncthreads();

    const float4* __restrict__ pin = xin + c;

    float4 acc = make_float4(0.f, 0.f, 0.f, 0.f);
    #pragma unroll
    for (int k = 0; k < DEGREE; k += 8) {
        float  w[8];
        float4 v[8];
        #pragma unroll
        for (int u = 0; u < 8; u++) {
            int2 wd = s_wd[r][k + u];
            w[u] = __int_as_float(wd.y);
            v[u] = pin[wd.x * D4];
        }
        #pragma unroll
        for (int u = 0; u < 8; u++) {
            acc.x += w[u] * v[u].x;
            acc.y += w[u] * v[u].y;
            acc.z += w[u] * v[u].z;
            acc.w += w[u] * v[u].w;
        }
    }

    int oidx = row * D4 + c;
    if (t == 1) {
        g_x0[oidx] = acc;
        out[oidx]  = acc;                       // init tap (d_out is poisoned)
    } else {
        // write bf16 for the bf16 chain (features 4c..4c+3 -> 8 bytes)
        __nv_bfloat162 p0 = __floats2bfloat162_rn(acc.x, acc.y);
        __nv_bfloat162 p1 = __floats2bfloat162_rn(acc.z, acc.w);
        uint2 o;
        o.x = *reinterpret_cast<unsigned int*>(&p0);
        o.y = *reinterpret_cast<unsigned int*>(&p1);
        ((uint2*)g_b0)[row * 64 + c] = o;
        float4 a = out[oidx];
        a.x += acc.x; a.y += acc.y; a.z += acc.z; a.w += acc.w;
        out[oidx] = a;                          // tap scale 1.0
    }
}

// ---------------------------------------------------------------------------
// bf16 step (t=3..32): 8 rows/CTA, 32 threads/row, 8 bf16 (16B) per thread.
// Gather bf16 rows, unpack to fp32, FMA in fp32, repack to bf16.
// Buffer parity: t odd reads g_b0 / writes g_b1, t even the reverse
// (t=2 wrote g_b0). Taps at t=4 (1/2), 8 (1/6), 16 (1/24), 32 (1/120)
// accumulate fp32 into out. t=32 skips the bf16 store.
// ---------------------------------------------------------------------------
__global__ void __launch_bounds__(256, 4)
spmm_b16(int t, float4* __restrict__ out, float scale) {
    __shared__ int2 s_wd[8 * DEGREE];

    const uint4* __restrict__ xin  = (t & 1) ? g_b0 : g_b1;
    uint4*       __restrict__ xout = (t & 1) ? g_b1 : g_b0;

    int tid = threadIdx.x;
    int r   = tid >> 5;        // row within block (0..7)
    int c   = tid & 31;        // 16B granule (0..31)
    int row = blockIdx.x * 8 + r;

    s_wd[tid] = g_wd[blockIdx.x * (8 * DEGREE) + tid];
    __syncthreads();

    const uint4* __restrict__ pin = xin + c;

    float acc[8] = {0.f, 0.f, 0.f, 0.f, 0.f, 0.f, 0.f, 0.f};
    #pragma unroll
    for (int k = 0; k < DEGREE; k += 8) {
        float w[8];
        uint4 v[8];
        #pragma unroll
        for (int u = 0; u < 8; u++) {
            int2 wd = s_wd[r * DEGREE + k + u];
            w[u] = __int_as_float(wd.y);
            v[u] = pin[wd.x * G16];
        }
        #pragma unroll
        for (int u = 0; u < 8; u++) {
            float2 f0 = __bfloat1622float2(*reinterpret_cast<__nv_bfloat162*>(&v[u].x));
            float2 f1 = __bfloat1622float2(*reinterpret_cast<__nv_bfloat162*>(&v[u].y));
            float2 f2 = __bfloat1622float2(*reinterpret_cast<__nv_bfloat162*>(&v[u].z));
            float2 f3 = __bfloat1622float2(*reinterpret_cast<__nv_bfloat162*>(&v[u].w));
            acc[0] += w[u] * f0.x;  acc[1] += w[u] * f0.y;
            acc[2] += w[u] * f1.x;  acc[3] += w[u] * f1.y;
            acc[4] += w[u] * f2.x;  acc[5] += w[u] * f2.y;
            acc[6] += w[u] * f3.x;  acc[7] += w[u] * f3.y;
        }
    }

    if (t != 32) {
        __nv_bfloat162 p0 = __floats2bfloat162_rn(acc[0], acc[1]);
        __nv_bfloat162 p1 = __floats2bfloat162_rn(acc[2], acc[3]);
        __nv_bfloat162 p2 = __floats2bfloat162_rn(acc[4], acc[5]);
        __nv_bfloat162 p3 = __floats2bfloat162_rn(acc[6], acc[7]);
        uint4 o;
        o.x = *reinterpret_cast<unsigned int*>(&p0);
        o.y = *reinterpret_cast<unsigned int*>(&p1);
        o.z = *reinterpret_cast<unsigned int*>(&p2);
        o.w = *reinterpret_cast<unsigned int*>(&p3);
        xout[row * G16 + c] = o;
    }

    if (scale != 0.0f) {
        // thread covers features c*8 .. c*8+7 -> two float4 slots
        int ob = row * D4 + c * 2;
        float4 a0 = out[ob];
        float4 a1 = out[ob + 1];
        a0.x += scale * acc[0];  a0.y += scale * acc[1];
        a0.z += scale * acc[2];  a0.w += scale * acc[3];
        a1.x += scale * acc[4];  a1.y += scale * acc[5];
        a1.z += scale * acc[6];  a1.w += scale * acc[7];
        out[ob]     = a0;
        out[ob + 1] = a1;
    }
}

// ---------------------------------------------------------------------------
// inputs (metadata order): src(int), dst(int), e(float32), h(float32)
// output: float32 [N_NODES, D_FEAT]
//
// out = A h + (A^2 h)/1! + (A^4 h)/2! + (A^8 h)/3! + (A^16 h)/4! + (A^32 h)/5!
// computed as 32 sparse applications: t=1,2 fp32 (dominant taps), t=3..32
// bf16 iterates with fp32 accumulation (taps 1/2, 1/6, 1/24, 1/120).
// ---------------------------------------------------------------------------
extern "C" void kernel_launch(void* const* d_in, const int* in_sizes, int n_in,
                              void* d_out, int out_size) {
    const void*   dst = d_in[1];
    const float*  e   = (const float*)d_in[2];
    const float4* h   = (const float4*)d_in[3];
    float4*       out = (float4*)d_out;

    prep_kernel<<<N_EDGES / 256, 256>>>(dst, e);

    spmm_f32<<<N_NODES / 4, 256>>>(h, 1, out);
    spmm_f32<<<N_NODES / 4, 256>>>(h, 2, out);

    for (int t = 3; t <= 32; t++) {
        float scale = 0.0f;
        switch (t) {
            case 4:  scale = 1.0f / 2.0f;   break;
            case 8:  scale = 1.0f / 6.0f;   break;
            case 16: scale = 1.0f / 24.0f;  break;
            case 32: scale = 1.0f / 120.0f; break;
            default: break;
        }
        spmm_b16<<<N_NODES / 8, 256>>>(t, out, scale);
    }
}

// round 4
// speedup vs baseline: 1.5116x; 1.0791x over previous
#include <cuda_runtime.h>
#include <cuda_bf16.h>

#define N_NODES 8192
#define DEGREE  32
#define N_EDGES (N_NODES * DEGREE)
#define D_FEAT  256
#define D4      (D_FEAT / 4)            // 64 float4 columns per fp32 row
#define G16     (D_FEAT / 8)            // 32 16B granules per bf16 row

// ---- device scratch (static; no allocation anywhere) ----
__device__ int2   g_wd32[N_EDGES];        // {dst, fp32 weight bits}       (fp32 steps)
__device__ int2   g_wdb [N_EDGES];        // {dst*512 bytes, bf16x2 weight} (bf16 steps)
__device__ float4 g_x0[N_NODES * D4];     // fp32 buffer (t=1 output)
__device__ uint4  g_b0[N_NODES * G16];    // bf16 ping
__device__ uint4  g_b1[N_NODES * G16];    // bf16 pong

// ---------------------------------------------------------------------------
// Prep: per-row weight normalization + dst decode. One warp per node row
// (DEGREE == 32 lanes). src is structurally repeat(arange(N_NODES), DEGREE),
// so edge j belongs to row j / DEGREE. Duplicate (src,dst) pairs accumulate
// linearly in the weighted sum, matching COO .add + row-normalization.
// int64-vs-int32 dst detection: dst in [0,8192), so little-endian int64
// storage means every odd 32-bit word of the first 64 words is zero.
// ---------------------------------------------------------------------------
__global__ void prep_kernel(const void* __restrict__ dst_raw,
                            const float* __restrict__ e) {
    const int* p = (const int*)dst_raw;
    int is64 = 1;
    #pragma unroll
    for (int k = 1; k < 64; k += 2) is64 &= (p[k] == 0);

    int warp = (blockIdx.x * blockDim.x + threadIdx.x) >> 5;
    int lane = threadIdx.x & 31;
    if (warp >= N_NODES) return;
    int j = warp * DEGREE + lane;

    float ev = e[j];
    float s  = ev;
    #pragma unroll
    for (int o = 16; o > 0; o >>= 1) s += __shfl_xor_sync(0xffffffffu, s, o);
    float w = ev / s;

    int d;
    if (is64) d = (int)((const long long*)dst_raw)[j];
    else      d = ((const int*)dst_raw)[j];

    g_wd32[j] = make_int2(d, __float_as_int(w));

    __nv_bfloat162 w2 = __float2bfloat162_rn(w);   // both halves = w
    g_wdb[j] = make_int2(d * 512, *reinterpret_cast<int*>(&w2));
}

// ---------------------------------------------------------------------------
// fp32 step (t=1,2): xout[r] = sum_k w[r,k] * xin[dst[r,k]]
//   t=1: in = h (ext), out = g_x0 fp32, tap 1.0 (init d_out)
//   t=2: in = g_x0,    out = g_b0 bf16, tap 1.0
// 4 rows/CTA, 64 threads/row, float4 gathers, MLP=8.
// ---------------------------------------------------------------------------
__global__ void __launch_bounds__(256, 4)
spmm_f32(const float4* __restrict__ xin_ext, int t, float4* __restrict__ out) {
    __shared__ int2 s_wd[4][DEGREE];

    const float4* __restrict__ xin = (t == 1) ? xin_ext : g_x0;

    int tid = threadIdx.x;
    int r   = tid >> 6;        // row within block (0..3)
    int c   = tid & 63;        // float4 column (0..63)
    int row = blockIdx.x * 4 + r;

    if (tid < 4 * DEGREE) {
        int rr = tid >> 5, kk = tid & 31;
        s_wd[rr][kk] = g_wd32[(blockIdx.x * 4 + rr) * DEGREE + kk];
    }
    __syncthreads();

    const float4* __restrict__ pin = xin + c;

    float4 acc = make_float4(0.f, 0.f, 0.f, 0.f);
    #pragma unroll
    for (int k = 0; k < DEGREE; k += 8) {
        float  w[8];
        float4 v[8];
        #pragma unroll
        for (int u = 0; u < 8; u++) {
            int2 wd = s_wd[r][k + u];
            w[u] = __int_as_float(wd.y);
            v[u] = pin[wd.x * D4];
        }
        #pragma unroll
        for (int u = 0; u < 8; u++) {
            acc.x += w[u] * v[u].x;
            acc.y += w[u] * v[u].y;
            acc.z += w[u] * v[u].z;
            acc.w += w[u] * v[u].w;
        }
    }

    int oidx = row * D4 + c;
    if (t == 1) {
        g_x0[oidx] = acc;
        out[oidx]  = acc;                       // init tap (d_out is poisoned)
    } else {
        // write bf16 for the bf16 chain (features 4c..4c+3 -> 8 bytes)
        __nv_bfloat162 p0 = __floats2bfloat162_rn(acc.x, acc.y);
        __nv_bfloat162 p1 = __floats2bfloat162_rn(acc.z, acc.w);
        uint2 o;
        o.x = *reinterpret_cast<unsigned int*>(&p0);
        o.y = *reinterpret_cast<unsigned int*>(&p1);
        ((uint2*)g_b0)[row * 64 + c] = o;
        float4 a = out[oidx];
        a.x += acc.x; a.y += acc.y; a.z += acc.z; a.w += acc.w;
        out[oidx] = a;                          // tap scale 1.0
    }
}

// ---------------------------------------------------------------------------
// bf16 step (t=3..32): one warp per row, 32 threads x 16B = 512B row.
// Packed bf16 HFMA2 accumulation in 4 independent chains (8 edges each) to
// bound the rounding random-walk; chains combined with HADD2. Store is the
// raw bf16x2 accumulators (no repack). Taps at t=4 (1/2), 8 (1/6), 16 (1/24),
// 32 (1/120) unpack to fp32 and accumulate into out. t=32 skips the store.
// Buffer parity: t odd reads g_b0 / writes g_b1 (t=2 wrote g_b0).
// ---------------------------------------------------------------------------
__global__ void __launch_bounds__(256)
spmm_b16(int t, float4* __restrict__ out, float scale) {
    __shared__ int2 s_wd[8][DEGREE];

    const uint4* __restrict__ xin  = (t & 1) ? g_b0 : g_b1;
    uint4*       __restrict__ xout = (t & 1) ? g_b1 : g_b0;

    int tid = threadIdx.x;
    int r   = tid >> 5;        // warp within block = row (0..7)
    int c   = tid & 31;        // 16B granule (0..31)
    int row = blockIdx.x * 8 + r;

    // each warp loads its own row's edge list; warp-private smem region
    s_wd[r][c] = g_wdb[row * DEGREE + c];
    __syncwarp();

    const char* __restrict__ base = (const char*)xin + c * 16;

    __nv_bfloat162 z = __float2bfloat162_rn(0.f);
    __nv_bfloat162 A[4][4];    // [chain][feature pair]
    #pragma unroll
    for (int q = 0; q < 4; q++)
        #pragma unroll
        for (int pp = 0; pp < 4; pp++) A[q][pp] = z;

    #pragma unroll
    for (int k = 0; k < DEGREE; k += 4) {
        int2 wd0 = s_wd[r][k + 0];
        int2 wd1 = s_wd[r][k + 1];
        int2 wd2 = s_wd[r][k + 2];
        int2 wd3 = s_wd[r][k + 3];
        uint4 v0 = *reinterpret_cast<const uint4*>(base + wd0.x);
        uint4 v1 = *reinterpret_cast<const uint4*>(base + wd1.x);
        uint4 v2 = *reinterpret_cast<const uint4*>(base + wd2.x);
        uint4 v3 = *reinterpret_cast<const uint4*>(base + wd3.x);
        __nv_bfloat162 w0 = *reinterpret_cast<__nv_bfloat162*>(&wd0.y);
        __nv_bfloat162 w1 = *reinterpret_cast<__nv_bfloat162*>(&wd1.y);
        __nv_bfloat162 w2 = *reinterpret_cast<__nv_bfloat162*>(&wd2.y);
        __nv_bfloat162 w3 = *reinterpret_cast<__nv_bfloat162*>(&wd3.y);
        const __nv_bfloat162* b0 = reinterpret_cast<const __nv_bfloat162*>(&v0);
        const __nv_bfloat162* b1 = reinterpret_cast<const __nv_bfloat162*>(&v1);
        const __nv_bfloat162* b2 = reinterpret_cast<const __nv_bfloat162*>(&v2);
        const __nv_bfloat162* b3 = reinterpret_cast<const __nv_bfloat162*>(&v3);
        #pragma unroll
        for (int pp = 0; pp < 4; pp++) {
            A[0][pp] = __hfma2(w0, b0[pp], A[0][pp]);
            A[1][pp] = __hfma2(w1, b1[pp], A[1][pp]);
            A[2][pp] = __hfma2(w2, b2[pp], A[2][pp]);
            A[3][pp] = __hfma2(w3, b3[pp], A[3][pp]);
        }
    }

    // combine the 4 chains
    __nv_bfloat162 res[4];
    #pragma unroll
    for (int pp = 0; pp < 4; pp++)
        res[pp] = __hadd2(__hadd2(A[0][pp], A[1][pp]),
                          __hadd2(A[2][pp], A[3][pp]));

    if (t != 32) {
        uint4 o;
        o.x = *reinterpret_cast<unsigned int*>(&res[0]);
        o.y = *reinterpret_cast<unsigned int*>(&res[1]);
        o.z = *reinterpret_cast<unsigned int*>(&res[2]);
        o.w = *reinterpret_cast<unsigned int*>(&res[3]);
        xout[row * G16 + c] = o;
    }

    if (scale != 0.0f) {
        float2 f0 = __bfloat1622float2(res[0]);
        float2 f1 = __bfloat1622float2(res[1]);
        float2 f2 = __bfloat1622float2(res[2]);
        float2 f3 = __bfloat1622float2(res[3]);
        int ob = row * D4 + c * 2;      // features c*8 .. c*8+7
        float4 a0 = out[ob];
        float4 a1 = out[ob + 1];
        a0.x += scale * f0.x;  a0.y += scale * f0.y;
        a0.z += scale * f1.x;  a0.w += scale * f1.y;
        a1.x += scale * f2.x;  a1.y += scale * f2.y;
        a1.z += scale * f3.x;  a1.w += scale * f3.y;
        out[ob]     = a0;
        out[ob + 1] = a1;
    }
}

// ---------------------------------------------------------------------------
// inputs (metadata order): src(int), dst(int), e(float32), h(float32)
// output: float32 [N_NODES, D_FEAT]
//
// out = A h + (A^2 h)/1! + (A^4 h)/2! + (A^8 h)/3! + (A^16 h)/4! + (A^32 h)/5!
// computed as 32 sparse applications: t=1,2 fp32 (dominant taps), t=3..32
// bf16 HFMA2 iterates (taps 1/2, 1/6, 1/24, 1/120 accumulated in fp32).
// ---------------------------------------------------------------------------
extern "C" void kernel_launch(void* const* d_in, const int* in_sizes, int n_in,
                              void* d_out, int out_size) {
    const void*   dst = d_in[1];
    const float*  e   = (const float*)d_in[2];
    const float4* h   = (const float4*)d_in[3];
    float4*       out = (float4*)d_out;

    prep_kernel<<<N_EDGES / 256, 256>>>(dst, e);

    spmm_f32<<<N_NODES / 4, 256>>>(h, 1, out);
    spmm_f32<<<N_NODES / 4, 256>>>(h, 2, out);

    for (int t = 3; t <= 32; t++) {
        float scale = 0.0f;
        switch (t) {
            case 4:  scale = 1.0f / 2.0f;   break;
            case 8:  scale = 1.0f / 6.0f;   break;
            case 16: scale = 1.0f / 24.0f;  break;
            case 32: scale = 1.0f / 120.0f; break;
            default: break;
        }
        spmm_b16<<<N_NODES / 8, 256>>>(t, out, scale);
    }
}

// round 5
// speedup vs baseline: 1.9118x; 1.2648x over previous
#include <cuda_runtime.h>
#include <cuda_bf16.h>
#include <cuda_fp16.h>

#define N_NODES 8192
#define DEGREE  32
#define N_EDGES (N_NODES * DEGREE)
#define D_FEAT  256
#define D4      (D_FEAT / 4)            // 64 float4 columns per fp32 row
#define G16     (D_FEAT / 8)            // 32 16B granules per bf16 row
#define G8      (D_FEAT / 8)            // 32  8B granules per fp8 row

// ---- device scratch (static; no allocation anywhere) ----
__device__ int2   g_wd32[N_EDGES];        // {dst, fp32 weight bits}
__device__ int2   g_wdb [N_EDGES];        // {dst*512B, bf16x2 weight}
__device__ int2   g_wdf [N_EDGES];        // {dst*256B, half2 weight}
__device__ float4 g_x0[N_NODES * D4];     // fp32 buffer (t=1 output)
__device__ uint4  g_b0[N_NODES * G16];    // bf16 ping
__device__ uint4  g_b1[N_NODES * G16];    // bf16 pong
__device__ uint2  g_f0[N_NODES * G8];     // fp8 ping  (holds 32*x)
__device__ uint2  g_f1[N_NODES * G8];     // fp8 pong

// ---- fp8 <-> half2 helpers --------------------------------------------------
__device__ __forceinline__ unsigned pack_e4m3(__half2 a, __half2 b) {
    unsigned r;
    asm("{ .reg .b16 lo, hi;\n\t"
        "cvt.rn.satfinite.e4m3x2.f16x2 lo, %1;\n\t"
        "cvt.rn.satfinite.e4m3x2.f16x2 hi, %2;\n\t"
        "mov.b32 %0, {lo, hi}; }"
        : "=r"(r)
        : "r"(*reinterpret_cast<unsigned*>(&a)),
          "r"(*reinterpret_cast<unsigned*>(&b)));
    return r;
}

__device__ __forceinline__ void unpack_e4m3(unsigned v, __half2& a, __half2& b) {
    unsigned ra, rb;
    asm("{ .reg .b16 lo, hi;\n\t"
        "mov.b32 {lo, hi}, %2;\n\t"
        "cvt.rn.f16x2.e4m3x2 %0, lo;\n\t"
        "cvt.rn.f16x2.e4m3x2 %1, hi; }"
        : "=r"(ra), "=r"(rb) : "r"(v));
    a = *reinterpret_cast<__half2*>(&ra);
    b = *reinterpret_cast<__half2*>(&rb);
}

// ---------------------------------------------------------------------------
// Prep: per-row weight normalization + dst decode. One warp per node row.
// src is structurally repeat(arange(N_NODES), DEGREE), so edge j belongs to
// row j / DEGREE. Duplicate (src,dst) pairs accumulate linearly in the
// weighted sum, matching COO .add + row-normalization semantics.
// int64-vs-int32 dst detection: dst in [0,8192), so little-endian int64
// storage means every odd 32-bit word of the first 64 words is zero.
// ---------------------------------------------------------------------------
__global__ void prep_kernel(const void* __restrict__ dst_raw,
                            const float* __restrict__ e) {
    const int* p = (const int*)dst_raw;
    int is64 = 1;
    #pragma unroll
    for (int k = 1; k < 64; k += 2) is64 &= (p[k] == 0);

    int warp = (blockIdx.x * blockDim.x + threadIdx.x) >> 5;
    int lane = threadIdx.x & 31;
    if (warp >= N_NODES) return;
    int j = warp * DEGREE + lane;

    float ev = e[j];
    float s  = ev;
    #pragma unroll
    for (int o = 16; o > 0; o >>= 1) s += __shfl_xor_sync(0xffffffffu, s, o);
    float w = ev / s;

    int d;
    if (is64) d = (int)((const long long*)dst_raw)[j];
    else      d = ((const int*)dst_raw)[j];

    g_wd32[j] = make_int2(d, __float_as_int(w));

    __nv_bfloat162 wb = __float2bfloat162_rn(w);
    g_wdb[j] = make_int2(d * 512, *reinterpret_cast<int*>(&wb));

    __half2 wh = __float2half2_rn(w);
    g_wdf[j] = make_int2(d * 256, *reinterpret_cast<int*>(&wh));
}

// ---------------------------------------------------------------------------
// fp32 step (t=1,2): 4 rows/CTA, 64 threads/row, float4 gathers, MLP=8.
//   t=1: in = h (ext), out = g_x0 fp32, tap 1.0 (init d_out)
//   t=2: in = g_x0,    out = g_b0 bf16, tap 1.0
// ---------------------------------------------------------------------------
__global__ void __launch_bounds__(256, 4)
spmm_f32(const float4* __restrict__ xin_ext, int t, float4* __restrict__ out) {
    __shared__ int2 s_wd[4][DEGREE];

    const float4* __restrict__ xin = (t == 1) ? xin_ext : g_x0;

    int tid = threadIdx.x;
    int r   = tid >> 6;
    int c   = tid & 63;
    int row = blockIdx.x * 4 + r;

    if (tid < 4 * DEGREE) {
        int rr = tid >> 5, kk = tid & 31;
        s_wd[rr][kk] = g_wd32[(blockIdx.x * 4 + rr) * DEGREE + kk];
    }
    __syncthreads();

    const float4* __restrict__ pin = xin + c;

    float4 acc = make_float4(0.f, 0.f, 0.f, 0.f);
    #pragma unroll
    for (int k = 0; k < DEGREE; k += 8) {
        float  w[8];
        float4 v[8];
        #pragma unroll
        for (int u = 0; u < 8; u++) {
            int2 wd = s_wd[r][k + u];
            w[u] = __int_as_float(wd.y);
            v[u] = pin[wd.x * D4];
        }
        #pragma unroll
        for (int u = 0; u < 8; u++) {
            acc.x += w[u] * v[u].x;
            acc.y += w[u] * v[u].y;
            acc.z += w[u] * v[u].z;
            acc.w += w[u] * v[u].w;
        }
    }

    int oidx = row * D4 + c;
    if (t == 1) {
        g_x0[oidx] = acc;
        out[oidx]  = acc;                       // init tap (d_out is poisoned)
    } else {
        __nv_bfloat162 p0 = __floats2bfloat162_rn(acc.x, acc.y);
        __nv_bfloat162 p1 = __floats2bfloat162_rn(acc.z, acc.w);
        uint2 o;
        o.x = *reinterpret_cast<unsigned int*>(&p0);
        o.y = *reinterpret_cast<unsigned int*>(&p1);
        ((uint2*)g_b0)[row * 64 + c] = o;
        float4 a = out[oidx];
        a.x += acc.x; a.y += acc.y; a.z += acc.z; a.w += acc.w;
        out[oidx] = a;                          // tap scale 1.0
    }
}

// ---------------------------------------------------------------------------
// bf16 step (t=3,4): one warp per row, 32 threads x 16B = 512B row.
// Packed bf16 HFMA2 in 4 independent chains. t=3: bf16 store (g_b0 -> g_b1).
// t=4: taps 1/2 in fp32, stores 32*x as e4m3 into g_f0 for the fp8 chain.
// ---------------------------------------------------------------------------
__global__ void __launch_bounds__(256)
spmm_b16(int t, float4* __restrict__ out, float scale, int to_f8) {
    __shared__ int2 s_wd[8][DEGREE];

    const uint4* __restrict__ xin  = (t & 1) ? g_b0 : g_b1;
    uint4*       __restrict__ xout = (t & 1) ? g_b1 : g_b0;

    int tid = threadIdx.x;
    int r   = tid >> 5;
    int c   = tid & 31;
    int row = blockIdx.x * 8 + r;

    s_wd[r][c] = g_wdb[row * DEGREE + c];
    __syncwarp();

    const char* __restrict__ base = (const char*)xin + c * 16;

    __nv_bfloat162 z = __float2bfloat162_rn(0.f);
    __nv_bfloat162 A[4][4];
    #pragma unroll
    for (int q = 0; q < 4; q++)
        #pragma unroll
        for (int pp = 0; pp < 4; pp++) A[q][pp] = z;

    #pragma unroll
    for (int k = 0; k < DEGREE; k += 4) {
        int2 wd0 = s_wd[r][k + 0];
        int2 wd1 = s_wd[r][k + 1];
        int2 wd2 = s_wd[r][k + 2];
        int2 wd3 = s_wd[r][k + 3];
        uint4 v0 = *reinterpret_cast<const uint4*>(base + wd0.x);
        uint4 v1 = *reinterpret_cast<const uint4*>(base + wd1.x);
        uint4 v2 = *reinterpret_cast<const uint4*>(base + wd2.x);
        uint4 v3 = *reinterpret_cast<const uint4*>(base + wd3.x);
        __nv_bfloat162 w0 = *reinterpret_cast<__nv_bfloat162*>(&wd0.y);
        __nv_bfloat162 w1 = *reinterpret_cast<__nv_bfloat162*>(&wd1.y);
        __nv_bfloat162 w2 = *reinterpret_cast<__nv_bfloat162*>(&wd2.y);
        __nv_bfloat162 w3 = *reinterpret_cast<__nv_bfloat162*>(&wd3.y);
        const __nv_bfloat162* b0 = reinterpret_cast<const __nv_bfloat162*>(&v0);
        const __nv_bfloat162* b1 = reinterpret_cast<const __nv_bfloat162*>(&v1);
        const __nv_bfloat162* b2 = reinterpret_cast<const __nv_bfloat162*>(&v2);
        const __nv_bfloat162* b3 = reinterpret_cast<const __nv_bfloat162*>(&v3);
        #pragma unroll
        for (int pp = 0; pp < 4; pp++) {
            A[0][pp] = __hfma2(w0, b0[pp], A[0][pp]);
            A[1][pp] = __hfma2(w1, b1[pp], A[1][pp]);
            A[2][pp] = __hfma2(w2, b2[pp], A[2][pp]);
            A[3][pp] = __hfma2(w3, b3[pp], A[3][pp]);
        }
    }

    __nv_bfloat162 res[4];
    #pragma unroll
    for (int pp = 0; pp < 4; pp++)
        res[pp] = __hadd2(__hadd2(A[0][pp], A[1][pp]),
                          __hadd2(A[2][pp], A[3][pp]));

    float2 f0 = __bfloat1622float2(res[0]);
    float2 f1 = __bfloat1622float2(res[1]);
    float2 f2 = __bfloat1622float2(res[2]);
    float2 f3 = __bfloat1622float2(res[3]);

    if (to_f8) {
        // store 32*x as e4m3 (scale keeps values ~0.35 rms, off subnormals)
        __half2 h0 = __floats2half2_rn(32.f * f0.x, 32.f * f0.y);
        __half2 h1 = __floats2half2_rn(32.f * f1.x, 32.f * f1.y);
        __half2 h2 = __floats2half2_rn(32.f * f2.x, 32.f * f2.y);
        __half2 h3 = __floats2half2_rn(32.f * f3.x, 32.f * f3.y);
        g_f0[row * G8 + c] = make_uint2(pack_e4m3(h0, h1), pack_e4m3(h2, h3));
    } else {
        uint4 o;
        o.x = *reinterpret_cast<unsigned int*>(&res[0]);
        o.y = *reinterpret_cast<unsigned int*>(&res[1]);
        o.z = *reinterpret_cast<unsigned int*>(&res[2]);
        o.w = *reinterpret_cast<unsigned int*>(&res[3]);
        xout[row * G16 + c] = o;
    }

    if (scale != 0.0f) {
        int ob = row * D4 + c * 2;
        float4 a0 = out[ob];
        float4 a1 = out[ob + 1];
        a0.x += scale * f0.x;  a0.y += scale * f0.y;
        a0.z += scale * f1.x;  a0.w += scale * f1.y;
        a1.x += scale * f2.x;  a1.y += scale * f2.y;
        a1.z += scale * f3.x;  a1.w += scale * f3.y;
        out[ob]     = a0;
        out[ob + 1] = a1;
    }
}

// ---------------------------------------------------------------------------
// fp8 step (t=5..32): one warp per row, 32 threads x 8B = 256B row.
// Buffers hold 32*x in e4m3. acc = sum_k w_k * v_k = 32 * x_next (fp16 HFMA2,
// 2 independent chains), re-stored directly (no rescale). Taps at t=8 (1/6),
// 16 (1/24), 32 (1/120) fold the /32 into the scale constant and accumulate
// fp32 into out. Parity: t odd reads g_f0 (t=4 wrote g_f0), writes g_f1.
// ---------------------------------------------------------------------------
__global__ void __launch_bounds__(256, 4)
spmm_f8(int t, float4* __restrict__ out, float scale) {
    __shared__ int2 s_wd[8][DEGREE];

    const uint2* __restrict__ xin  = (t & 1) ? g_f0 : g_f1;
    uint2*       __restrict__ xout = (t & 1) ? g_f1 : g_f0;

    int tid = threadIdx.x;
    int r   = tid >> 5;
    int c   = tid & 31;
    int row = blockIdx.x * 8 + r;

    s_wd[r][c] = g_wdf[row * DEGREE + c];
    __syncwarp();

    const char* __restrict__ base = (const char*)xin + c * 8;

    __half2 z = __floats2half2_rn(0.f, 0.f);
    __half2 A[2][4];
    #pragma unroll
    for (int q = 0; q < 2; q++)
        #pragma unroll
        for (int pp = 0; pp < 4; pp++) A[q][pp] = z;

    #pragma unroll
    for (int k = 0; k < DEGREE; k += 8) {
        int2  wd[8];
        uint2 v[8];
        #pragma unroll
        for (int u = 0; u < 8; u++) wd[u] = s_wd[r][k + u];
        #pragma unroll
        for (int u = 0; u < 8; u++)
            v[u] = *reinterpret_cast<const uint2*>(base + wd[u].x);
        #pragma unroll
        for (int u = 0; u < 8; u++) {
            __half2 w2 = *reinterpret_cast<__half2*>(&wd[u].y);
            __half2 f0, f1, f2, f3;
            unpack_e4m3(v[u].x, f0, f1);
            unpack_e4m3(v[u].y, f2, f3);
            int q = u & 1;
            A[q][0] = __hfma2(w2, f0, A[q][0]);
            A[q][1] = __hfma2(w2, f1, A[q][1]);
            A[q][2] = __hfma2(w2, f2, A[q][2]);
            A[q][3] = __hfma2(w2, f3, A[q][3]);
        }
    }

    __half2 res[4];
    #pragma unroll
    for (int pp = 0; pp < 4; pp++) res[pp] = __hadd2(A[0][pp], A[1][pp]);

    if (t != 32)
        xout[row * G8 + c] = make_uint2(pack_e4m3(res[0], res[1]),
                                        pack_e4m3(res[2], res[3]));

    if (scale != 0.0f) {
        float2 f0 = __half22float2(res[0]);
        float2 f1 = __half22float2(res[1]);
        float2 f2 = __half22float2(res[2]);
        float2 f3 = __half22float2(res[3]);
        int ob = row * D4 + c * 2;
        float4 a0 = out[ob];
        float4 a1 = out[ob + 1];
        a0.x += scale * f0.x;  a0.y += scale * f0.y;
        a0.z += scale * f1.x;  a0.w += scale * f1.y;
        a1.x += scale * f2.x;  a1.y += scale * f2.y;
        a1.z += scale * f3.x;  a1.w += scale * f3.y;
        out[ob]     = a0;
        out[ob + 1] = a1;
    }
}

// ---------------------------------------------------------------------------
// inputs (metadata order): src(int), dst(int), e(float32), h(float32)
// output: float32 [N_NODES, D_FEAT]
//
// out = A h + (A^2 h)/1! + (A^4 h)/2! + (A^8 h)/3! + (A^16 h)/4! + (A^32 h)/5!
// via 32 sparse applications: t=1,2 fp32; t=3,4 bf16; t=5..32 e4m3 iterates
// (scaled by 32) with fp16 accumulation; all taps accumulated in fp32.
// ---------------------------------------------------------------------------
extern "C" void kernel_launch(void* const* d_in, const int* in_sizes, int n_in,
                              void* d_out, int out_size) {
    const void*   dst = d_in[1];
    const float*  e   = (const float*)d_in[2];
    const float4* h   = (const float4*)d_in[3];
    float4*       out = (float4*)d_out;

    prep_kernel<<<N_EDGES / 256, 256>>>(dst, e);

    spmm_f32<<<N_NODES / 4, 256>>>(h, 1, out);
    spmm_f32<<<N_NODES / 4, 256>>>(h, 2, out);

    spmm_b16<<<N_NODES / 8, 256>>>(3, out, 0.0f, 0);
    spmm_b16<<<N_NODES / 8, 256>>>(4, out, 0.5f, 1);

    for (int t = 5; t <= 32; t++) {
        float scale = 0.0f;
        switch (t) {
            case 8:  scale = 1.0f / (6.0f   * 32.0f); break;
            case 16: scale = 1.0f / (24.0f  * 32.0f); break;
            case 32: scale = 1.0f / (120.0f * 32.0f); break;
            default: break;
        }
        spmm_f8<<<N_NODES / 8, 256>>>(t, out, scale);
    }
}

// round 6
// speedup vs baseline: 2.0864x; 1.0913x over previous
#include <cuda_runtime.h>
#include <cuda_fp16.h>

#define N_NODES 8192
#define DEGREE  32
#define N_EDGES (N_NODES * DEGREE)
#define D_FEAT  256
#define D4      (D_FEAT / 4)            // 64 float4 columns per fp32 row

// ---- device scratch (static; no allocation anywhere) ----
__device__ int2  g_wd32[N_EDGES];         // {dst, fp32 weight bits}        (t=1)
__device__ int2  g_wdh [N_EDGES];         // {dst*512B, half2 weight}       (fp16 steps)
__device__ int2  g_wdf [N_EDGES];         // {dst*256B, half2 weight}       (fp8 steps)
__device__ uint4 g_h0[N_NODES * 32];      // fp16 ping (512B rows)
__device__ uint4 g_h1[N_NODES * 32];      // fp16 pong
__device__ uint2 g_f0[N_NODES * 32];      // fp8 ping (256B rows, holds 32*x)
__device__ uint2 g_f1[N_NODES * 32];      // fp8 pong
__device__ uint4 g_t4 [N_NODES * 32];     // tap buffer: x4   (fp16)
__device__ uint4 g_t8 [N_NODES * 32];     // tap buffer: 32*x8  (fp16)
__device__ uint4 g_t16[N_NODES * 32];     // tap buffer: 32*x16 (fp16)

// ---- fp8 <-> half2 helpers -------------------------------------------------
__device__ __forceinline__ unsigned pack_e4m3(__half2 a, __half2 b) {
    unsigned r;
    asm("{ .reg .b16 lo, hi;\n\t"
        "cvt.rn.satfinite.e4m3x2.f16x2 lo, %1;\n\t"
        "cvt.rn.satfinite.e4m3x2.f16x2 hi, %2;\n\t"
        "mov.b32 %0, {lo, hi}; }"
        : "=r"(r)
        : "r"(*reinterpret_cast<unsigned*>(&a)),
          "r"(*reinterpret_cast<unsigned*>(&b)));
    return r;
}

__device__ __forceinline__ void unpack_e4m3(unsigned v, __half2& a, __half2& b) {
    unsigned ra, rb;
    asm("{ .reg .b16 lo, hi;\n\t"
        "mov.b32 {lo, hi}, %2;\n\t"
        "cvt.rn.f16x2.e4m3x2 %0, lo;\n\t"
        "cvt.rn.f16x2.e4m3x2 %1, hi; }"
        : "=r"(ra), "=r"(rb) : "r"(v));
    a = *reinterpret_cast<__half2*>(&ra);
    b = *reinterpret_cast<__half2*>(&rb);
}

// ---------------------------------------------------------------------------
// Prep: per-row weight normalization + dst decode. One warp per node row.
// src is structurally repeat(arange(N_NODES), DEGREE), so edge j belongs to
// row j / DEGREE. Duplicate (src,dst) pairs accumulate linearly in the
// weighted sum, matching COO .add + row-normalization semantics.
// int64-vs-int32 dst detection: dst in [0,8192), so little-endian int64
// storage means every odd 32-bit word of the first 64 words is zero.
// ---------------------------------------------------------------------------
__global__ void prep_kernel(const void* __restrict__ dst_raw,
                            const float* __restrict__ e) {
    const int* p = (const int*)dst_raw;
    int is64 = 1;
    #pragma unroll
    for (int k = 1; k < 64; k += 2) is64 &= (p[k] == 0);

    int warp = (blockIdx.x * blockDim.x + threadIdx.x) >> 5;
    int lane = threadIdx.x & 31;
    if (warp >= N_NODES) return;
    int j = warp * DEGREE + lane;

    float ev = e[j];
    float s  = ev;
    #pragma unroll
    for (int o = 16; o > 0; o >>= 1) s += __shfl_xor_sync(0xffffffffu, s, o);
    float w = ev / s;

    int d;
    if (is64) d = (int)((const long long*)dst_raw)[j];
    else      d = ((const int*)dst_raw)[j];

    g_wd32[j] = make_int2(d, __float_as_int(w));

    __half2 wh = __float2half2_rn(w);
    int whb = *reinterpret_cast<int*>(&wh);
    g_wdh[j] = make_int2(d * 512, whb);
    g_wdf[j] = make_int2(d * 256, whb);
}

// ---------------------------------------------------------------------------
// t=1: x1 = A h (fp32 gathers of h). Writes out = x1 (tap 1, init of the
// poisoned d_out) and x1 as fp16 into g_h0 for the fp16 chain.
// 4 rows/CTA, 64 threads/row, MLP=8.
// ---------------------------------------------------------------------------
__global__ void __launch_bounds__(256, 4)
spmm_t1(const float4* __restrict__ h, float4* __restrict__ out) {
    __shared__ int2 s_wd[4][DEGREE];

    int tid = threadIdx.x;
    int r   = tid >> 6;
    int c   = tid & 63;
    int row = blockIdx.x * 4 + r;

    if (tid < 4 * DEGREE) {
        int rr = tid >> 5, kk = tid & 31;
        s_wd[rr][kk] = g_wd32[(blockIdx.x * 4 + rr) * DEGREE + kk];
    }
    __syncthreads();

    const float4* __restrict__ pin = h + c;

    float4 acc = make_float4(0.f, 0.f, 0.f, 0.f);
    #pragma unroll
    for (int k = 0; k < DEGREE; k += 8) {
        float  w[8];
        float4 v[8];
        #pragma unroll
        for (int u = 0; u < 8; u++) {
            int2 wd = s_wd[r][k + u];
            w[u] = __int_as_float(wd.y);
            v[u] = pin[wd.x * D4];
        }
        #pragma unroll
        for (int u = 0; u < 8; u++) {
            acc.x += w[u] * v[u].x;
            acc.y += w[u] * v[u].y;
            acc.z += w[u] * v[u].z;
            acc.w += w[u] * v[u].w;
        }
    }

    out[row * D4 + c] = acc;                        // tap 1 (fp32)

    __half2 p0 = __floats2half2_rn(acc.x, acc.y);
    __half2 p1 = __floats2half2_rn(acc.z, acc.w);
    uint2 o;
    o.x = *reinterpret_cast<unsigned*>(&p0);
    o.y = *reinterpret_cast<unsigned*>(&p1);
    ((uint2*)g_h0)[row * 64 + c] = o;               // fp16 x1 for t=2
}

// ---------------------------------------------------------------------------
// fp16 step (t=2,3,4): warp handles 2 rows sequentially; 32 lanes x 16B =
// 512B row; 4 independent HFMA2 chains per row. Grid 512 = single wave.
//   t=2: g_h0 -> g_h1, out += acc (fp32 r/w, tap 1.0)
//   t=3: g_h1 -> g_h0
//   t=4: g_h0 -> tap buffer g_t4 (fp16 acc) + fp8 g_f0 (32*acc)
// ---------------------------------------------------------------------------
__global__ void __launch_bounds__(256, 4)
spmm_f16(int t, float4* __restrict__ out) {
    __shared__ int2 s_wd[16 * DEGREE];

    const uint4* __restrict__ xin  = (t & 1) ? g_h1 : g_h0;
    uint4*       __restrict__ xout = (t & 1) ? g_h0 : g_h1;

    int tid = threadIdx.x;
    int wr  = tid >> 5;        // warp 0..7
    int c   = tid & 31;

    s_wd[tid]       = g_wdh[blockIdx.x * 512 + tid];
    s_wd[tid + 256] = g_wdh[blockIdx.x * 512 + tid + 256];
    __syncthreads();

    #pragma unroll
    for (int rb = 0; rb < 2; rb++) {
        int lrow = wr * 2 + rb;                    // local row 0..15
        int row  = blockIdx.x * 16 + lrow;
        const int2* swd = &s_wd[lrow * DEGREE];

        const char* __restrict__ base = (const char*)xin + c * 16;

        __half2 z = __floats2half2_rn(0.f, 0.f);
        __half2 A[4][4];
        #pragma unroll
        for (int q = 0; q < 4; q++)
            #pragma unroll
            for (int pp = 0; pp < 4; pp++) A[q][pp] = z;

        #pragma unroll
        for (int k = 0; k < DEGREE; k += 4) {
            int2 wd0 = swd[k + 0];
            int2 wd1 = swd[k + 1];
            int2 wd2 = swd[k + 2];
            int2 wd3 = swd[k + 3];
            uint4 v0 = *reinterpret_cast<const uint4*>(base + wd0.x);
            uint4 v1 = *reinterpret_cast<const uint4*>(base + wd1.x);
            uint4 v2 = *reinterpret_cast<const uint4*>(base + wd2.x);
            uint4 v3 = *reinterpret_cast<const uint4*>(base + wd3.x);
            __half2 w0 = *reinterpret_cast<__half2*>(&wd0.y);
            __half2 w1 = *reinterpret_cast<__half2*>(&wd1.y);
            __half2 w2 = *reinterpret_cast<__half2*>(&wd2.y);
            __half2 w3 = *reinterpret_cast<__half2*>(&wd3.y);
            const __half2* b0 = reinterpret_cast<const __half2*>(&v0);
            const __half2* b1 = reinterpret_cast<const __half2*>(&v1);
            const __half2* b2 = reinterpret_cast<const __half2*>(&v2);
            const __half2* b3 = reinterpret_cast<const __half2*>(&v3);
            #pragma unroll
            for (int pp = 0; pp < 4; pp++) {
                A[0][pp] = __hfma2(w0, b0[pp], A[0][pp]);
                A[1][pp] = __hfma2(w1, b1[pp], A[1][pp]);
                A[2][pp] = __hfma2(w2, b2[pp], A[2][pp]);
                A[3][pp] = __hfma2(w3, b3[pp], A[3][pp]);
            }
        }

        __half2 res[4];
        #pragma unroll
        for (int pp = 0; pp < 4; pp++)
            res[pp] = __hadd2(__hadd2(A[0][pp], A[1][pp]),
                              __hadd2(A[2][pp], A[3][pp]));

        if (t != 4) {
            uint4 o;
            o.x = *reinterpret_cast<unsigned*>(&res[0]);
            o.y = *reinterpret_cast<unsigned*>(&res[1]);
            o.z = *reinterpret_cast<unsigned*>(&res[2]);
            o.w = *reinterpret_cast<unsigned*>(&res[3]);
            xout[row * 32 + c] = o;
        }

        if (t == 2) {
            float2 f0 = __half22float2(res[0]);
            float2 f1 = __half22float2(res[1]);
            float2 f2 = __half22float2(res[2]);
            float2 f3 = __half22float2(res[3]);
            int ob = row * D4 + c * 2;          // features c*8 .. c*8+7
            float4 a0 = out[ob];
            float4 a1 = out[ob + 1];
            a0.x += f0.x;  a0.y += f0.y;  a0.z += f1.x;  a0.w += f1.y;
            a1.x += f2.x;  a1.y += f2.y;  a1.z += f3.x;  a1.w += f3.y;
            out[ob]     = a0;
            out[ob + 1] = a1;
        } else if (t == 4) {
            uint4 tv;
            tv.x = *reinterpret_cast<unsigned*>(&res[0]);
            tv.y = *reinterpret_cast<unsigned*>(&res[1]);
            tv.z = *reinterpret_cast<unsigned*>(&res[2]);
            tv.w = *reinterpret_cast<unsigned*>(&res[3]);
            g_t4[row * 32 + c] = tv;            // tap buffer: x4 (fp16)

            __half2 s32 = __floats2half2_rn(32.f, 32.f);
            __half2 q0 = __hmul2(res[0], s32);
            __half2 q1 = __hmul2(res[1], s32);
            __half2 q2 = __hmul2(res[2], s32);
            __half2 q3 = __hmul2(res[3], s32);
            g_f0[row * 32 + c] = make_uint2(pack_e4m3(q0, q1),
                                            pack_e4m3(q2, q3));
        }
    }
}

// ---------------------------------------------------------------------------
// fp8 step (t=5..32): warp handles 2 rows sequentially; 32 lanes x 8B = 256B
// row. Buffers hold 32*x in e4m3; acc = sum w*v = 32*x_next (fp16 HFMA2, 2
// chains), re-stored directly. Grid 512 = single wave.
//   t=8,16: store acc to fp16 tap buffers (no fp32 out traffic)
//   t=32:   final combine: out += t4/2 + t8/192 + t16/768 + acc/3840
// Parity: t=4 wrote g_f0; read = (t&1) ? g_f0 : g_f1.
// ---------------------------------------------------------------------------
__global__ void __launch_bounds__(256, 4)
spmm_f8(int t, float4* __restrict__ out) {
    __shared__ int2 s_wd[16 * DEGREE];

    const uint2* __restrict__ xin  = (t & 1) ? g_f0 : g_f1;
    uint2*       __restrict__ xout = (t & 1) ? g_f1 : g_f0;

    int tid = threadIdx.x;
    int wr  = tid >> 5;
    int c   = tid & 31;

    s_wd[tid]       = g_wdf[blockIdx.x * 512 + tid];
    s_wd[tid + 256] = g_wdf[blockIdx.x * 512 + tid + 256];
    __syncthreads();

    #pragma unroll
    for (int rb = 0; rb < 2; rb++) {
        int lrow = wr * 2 + rb;
        int row  = blockIdx.x * 16 + lrow;
        const int2* swd = &s_wd[lrow * DEGREE];

        const char* __restrict__ base = (const char*)xin + c * 8;

        __half2 z = __floats2half2_rn(0.f, 0.f);
        __half2 A[2][4];
        #pragma unroll
        for (int q = 0; q < 2; q++)
            #pragma unroll
            for (int pp = 0; pp < 4; pp++) A[q][pp] = z;

        #pragma unroll
        for (int k = 0; k < DEGREE; k += 8) {
            int2  wd[8];
            uint2 v[8];
            #pragma unroll
            for (int u = 0; u < 8; u++) wd[u] = swd[k + u];
            #pragma unroll
            for (int u = 0; u < 8; u++)
                v[u] = *reinterpret_cast<const uint2*>(base + wd[u].x);
            #pragma unroll
            for (int u = 0; u < 8; u++) {
                __half2 w2 = *reinterpret_cast<__half2*>(&wd[u].y);
                __half2 f0, f1, f2, f3;
                unpack_e4m3(v[u].x, f0, f1);
                unpack_e4m3(v[u].y, f2, f3);
                int q = u & 1;
                A[q][0] = __hfma2(w2, f0, A[q][0]);
                A[q][1] = __hfma2(w2, f1, A[q][1]);
                A[q][2] = __hfma2(w2, f2, A[q][2]);
                A[q][3] = __hfma2(w2, f3, A[q][3]);
            }
        }

        __half2 res[4];
        #pragma unroll
        for (int pp = 0; pp < 4; pp++) res[pp] = __hadd2(A[0][pp], A[1][pp]);

        if (t != 32)
            xout[row * 32 + c] = make_uint2(pack_e4m3(res[0], res[1]),
                                            pack_e4m3(res[2], res[3]));

        if (t == 8 || t == 16) {
            uint4 tv;
            tv.x = *reinterpret_cast<unsigned*>(&res[0]);
            tv.y = *reinterpret_cast<unsigned*>(&res[1]);
            tv.z = *reinterpret_cast<unsigned*>(&res[2]);
            tv.w = *reinterpret_cast<unsigned*>(&res[3]);
            if (t == 8) g_t8 [row * 32 + c] = tv;
            else        g_t16[row * 32 + c] = tv;
        } else if (t == 32) {
            // final combine; out currently holds x1 + x2
            uint4 t4v  = g_t4 [row * 32 + c];
            uint4 t8v  = g_t8 [row * 32 + c];
            uint4 t16v = g_t16[row * 32 + c];
            const __half2* h4  = reinterpret_cast<const __half2*>(&t4v);
            const __half2* h8  = reinterpret_cast<const __half2*>(&t8v);
            const __half2* h16 = reinterpret_cast<const __half2*>(&t16v);

            float fs[8];
            #pragma unroll
            for (int pp = 0; pp < 4; pp++) {
                float2 a4  = __half22float2(h4[pp]);
                float2 a8  = __half22float2(h8[pp]);
                float2 a16 = __half22float2(h16[pp]);
                float2 a32 = __half22float2(res[pp]);
                fs[pp*2]   = 0.5f*a4.x + a8.x*(1.f/192.f)
                           + a16.x*(1.f/768.f) + a32.x*(1.f/3840.f);
                fs[pp*2+1] = 0.5f*a4.y + a8.y*(1.f/192.f)
                           + a16.y*(1.f/768.f) + a32.y*(1.f/3840.f);
            }
            int ob = row * D4 + c * 2;
            float4 a0 = out[ob];
            float4 a1 = out[ob + 1];
            a0.x += fs[0];  a0.y += fs[1];  a0.z += fs[2];  a0.w += fs[3];
            a1.x += fs[4];  a1.y += fs[5];  a1.z += fs[6];  a1.w += fs[7];
            out[ob]     = a0;
            out[ob + 1] = a1;
        }
    }
}

// ---------------------------------------------------------------------------
// inputs (metadata order): src(int), dst(int), e(float32), h(float32)
// output: float32 [N_NODES, D_FEAT]
//
// out = A h + (A^2 h)/1! + (A^4 h)/2! + (A^8 h)/3! + (A^16 h)/4! + (A^32 h)/5!
// via 32 sparse applications: t=1 fp32, t=2..4 fp16, t=5..32 e4m3 (scaled 32)
// with fp16 accumulation. Taps 1,2 fp32 into out; taps 4,8,16 via fp16 side
// buffers folded into the final t=32 combine.
// ---------------------------------------------------------------------------
extern "C" void kernel_launch(void* const* d_in, const int* in_sizes, int n_in,
                              void* d_out, int out_size) {
    const void*   dst = d_in[1];
    const float*  e   = (const float*)d_in[2];
    const float4* h   = (const float4*)d_in[3];
    float4*       out = (float4*)d_out;

    prep_kernel<<<N_EDGES / 256, 256>>>(dst, e);

    spmm_t1<<<N_NODES / 4, 256>>>(h, out);

    spmm_f16<<<N_NODES / 16, 256>>>(2, out);
    spmm_f16<<<N_NODES / 16, 256>>>(3, out);
    spmm_f16<<<N_NODES / 16, 256>>>(4, out);

    for (int t = 5; t <= 32; t++)
        spmm_f8<<<N_NODES / 16, 256>>>(t, out);
}

// round 7
// speedup vs baseline: 2.3276x; 1.1156x over previous
#include <cuda_runtime.h>
#include <cuda_fp16.h>

#define N_NODES 8192
#define DEGREE  32
#define N_EDGES (N_NODES * DEGREE)
#define D_FEAT  256
#define D4      (D_FEAT / 4)            // 64 float4 columns per fp32 row

// ---- device scratch (static; no allocation anywhere) ----
__device__ int2  g_wdh[N_EDGES];          // {dst*512B, half2 weight} (fp16 rows)
__device__ int2  g_wdf[N_EDGES];          // {dst*256B, half2 weight} (fp8 rows)
__device__ uint4 g_hx[N_NODES * 32];      // h in fp16 (512B rows)
__device__ uint4 g_h0[N_NODES * 32];      // x1 in fp16
__device__ uint2 g_f0[N_NODES * 32];      // fp8 ping (256B rows, holds 32*x)
__device__ uint2 g_f1[N_NODES * 32];      // fp8 pong
__device__ uint4 g_t4 [N_NODES * 32];     // tap buffer: 32*x4  (fp16)
__device__ uint4 g_t8 [N_NODES * 32];     // tap buffer: 32*x8  (fp16)
__device__ uint4 g_t16[N_NODES * 32];     // tap buffer: 32*x16 (fp16)

// ---- fp8 <-> half2 helpers -------------------------------------------------
__device__ __forceinline__ unsigned pack_e4m3(__half2 a, __half2 b) {
    unsigned r;
    asm("{ .reg .b16 lo, hi;\n\t"
        "cvt.rn.satfinite.e4m3x2.f16x2 lo, %1;\n\t"
        "cvt.rn.satfinite.e4m3x2.f16x2 hi, %2;\n\t"
        "mov.b32 %0, {lo, hi}; }"
        : "=r"(r)
        : "r"(*reinterpret_cast<unsigned*>(&a)),
          "r"(*reinterpret_cast<unsigned*>(&b)));
    return r;
}

__device__ __forceinline__ void unpack_e4m3(unsigned v, __half2& a, __half2& b) {
    unsigned ra, rb;
    asm("{ .reg .b16 lo, hi;\n\t"
        "mov.b32 {lo, hi}, %2;\n\t"
        "cvt.rn.f16x2.e4m3x2 %0, lo;\n\t"
        "cvt.rn.f16x2.e4m3x2 %1, hi; }"
        : "=r"(ra), "=r"(rb) : "r"(v));
    a = *reinterpret_cast<__half2*>(&ra);
    b = *reinterpret_cast<__half2*>(&rb);
}

// ---------------------------------------------------------------------------
// Prep: per-row weight normalization + dst decode. One warp per node row.
// src is structurally repeat(arange(N_NODES), DEGREE), so edge j belongs to
// row j / DEGREE. Duplicate (src,dst) pairs accumulate linearly in the
// weighted sum, matching COO .add + row-normalization semantics.
// int64-vs-int32 dst detection: dst in [0,8192), so little-endian int64
// storage means every odd 32-bit word of the first 64 words is zero.
// ---------------------------------------------------------------------------
__global__ void prep_kernel(const void* __restrict__ dst_raw,
                            const float* __restrict__ e) {
    const int* p = (const int*)dst_raw;
    int is64 = 1;
    #pragma unroll
    for (int k = 1; k < 64; k += 2) is64 &= (p[k] == 0);

    int warp = (blockIdx.x * blockDim.x + threadIdx.x) >> 5;
    int lane = threadIdx.x & 31;
    if (warp >= N_NODES) return;
    int j = warp * DEGREE + lane;

    float ev = e[j];
    float s  = ev;
    #pragma unroll
    for (int o = 16; o > 0; o >>= 1) s += __shfl_xor_sync(0xffffffffu, s, o);
    float w = ev / s;

    int d;
    if (is64) d = (int)((const long long*)dst_raw)[j];
    else      d = ((const int*)dst_raw)[j];

    __half2 wh = __float2half2_rn(w);
    int whb = *reinterpret_cast<int*>(&wh);
    g_wdh[j] = make_int2(d * 512, whb);
    g_wdf[j] = make_int2(d * 256, whb);
}

// ---------------------------------------------------------------------------
// Convert h (fp32) -> g_hx (fp16). 131072 threads x 16 floats.
// ---------------------------------------------------------------------------
__global__ void cvt_h_kernel(const float4* __restrict__ h) {
    int i = blockIdx.x * blockDim.x + threadIdx.x;    // 0 .. 131071
    float4 a0 = h[i * 4 + 0];
    float4 a1 = h[i * 4 + 1];
    float4 a2 = h[i * 4 + 2];
    float4 a3 = h[i * 4 + 3];
    __half2 p0 = __floats2half2_rn(a0.x, a0.y);
    __half2 p1 = __floats2half2_rn(a0.z, a0.w);
    __half2 p2 = __floats2half2_rn(a1.x, a1.y);
    __half2 p3 = __floats2half2_rn(a1.z, a1.w);
    __half2 p4 = __floats2half2_rn(a2.x, a2.y);
    __half2 p5 = __floats2half2_rn(a2.z, a2.w);
    __half2 p6 = __floats2half2_rn(a3.x, a3.y);
    __half2 p7 = __floats2half2_rn(a3.z, a3.w);
    uint4 o0, o1;
    o0.x = *reinterpret_cast<unsigned*>(&p0);
    o0.y = *reinterpret_cast<unsigned*>(&p1);
    o0.z = *reinterpret_cast<unsigned*>(&p2);
    o0.w = *reinterpret_cast<unsigned*>(&p3);
    o1.x = *reinterpret_cast<unsigned*>(&p4);
    o1.y = *reinterpret_cast<unsigned*>(&p5);
    o1.z = *reinterpret_cast<unsigned*>(&p6);
    o1.w = *reinterpret_cast<unsigned*>(&p7);
    g_hx[i * 2 + 0] = o0;
    g_hx[i * 2 + 1] = o1;
}

// ---------------------------------------------------------------------------
// t=1: x1 = A h, gathering fp16 h with fp32 accumulation (dominant tap stays
// precise). Warp handles 2 rows; 32 lanes x 16B (8 features). Grid 512 =
// single wave. Writes out = x1 (fp32 tap 1, init of poisoned d_out) and x1
// as fp16 into g_h0 for t=2.
// ---------------------------------------------------------------------------
__global__ void __launch_bounds__(256, 4)
spmm_t1(float4* __restrict__ out) {
    __shared__ int2 s_wd[16 * DEGREE];

    int tid = threadIdx.x;
    int wr  = tid >> 5;
    int c   = tid & 31;

    s_wd[tid]       = g_wdh[blockIdx.x * 512 + tid];
    s_wd[tid + 256] = g_wdh[blockIdx.x * 512 + tid + 256];
    __syncthreads();

    #pragma unroll
    for (int rb = 0; rb < 2; rb++) {
        int lrow = wr * 2 + rb;
        int row  = blockIdx.x * 16 + lrow;
        const int2* swd = &s_wd[lrow * DEGREE];
        const char* __restrict__ base = (const char*)g_hx + c * 16;

        float acc[8] = {0.f, 0.f, 0.f, 0.f, 0.f, 0.f, 0.f, 0.f};
        #pragma unroll
        for (int k = 0; k < DEGREE; k += 4) {
            int2  wd[4];
            uint4 v[4];
            #pragma unroll
            for (int u = 0; u < 4; u++) wd[u] = swd[k + u];
            #pragma unroll
            for (int u = 0; u < 4; u++)
                v[u] = *reinterpret_cast<const uint4*>(base + wd[u].x);
            #pragma unroll
            for (int u = 0; u < 4; u++) {
                __half2 wh = *reinterpret_cast<__half2*>(&wd[u].y);
                float w = __half2float(__low2half(wh));
                const __half2* hv = reinterpret_cast<const __half2*>(&v[u]);
                #pragma unroll
                for (int pp = 0; pp < 4; pp++) {
                    float2 f = __half22float2(hv[pp]);
                    acc[pp * 2]     += w * f.x;
                    acc[pp * 2 + 1] += w * f.y;
                }
            }
        }

        int ob = row * D4 + c * 2;
        out[ob]     = make_float4(acc[0], acc[1], acc[2], acc[3]);
        out[ob + 1] = make_float4(acc[4], acc[5], acc[6], acc[7]);

        __half2 q0 = __floats2half2_rn(acc[0], acc[1]);
        __half2 q1 = __floats2half2_rn(acc[2], acc[3]);
        __half2 q2 = __floats2half2_rn(acc[4], acc[5]);
        __half2 q3 = __floats2half2_rn(acc[6], acc[7]);
        uint4 o;
        o.x = *reinterpret_cast<unsigned*>(&q0);
        o.y = *reinterpret_cast<unsigned*>(&q1);
        o.z = *reinterpret_cast<unsigned*>(&q2);
        o.w = *reinterpret_cast<unsigned*>(&q3);
        g_h0[row * 32 + c] = o;
    }
}

// ---------------------------------------------------------------------------
// t=2: x2 = A x1 from fp16 x1 (512B rows), fp16 HFMA2 in 4 chains.
// Writes tap out += x2 (fp32 r/w) and 32*x2 as e4m3 into g_f0 for the fp8
// chain. Warp handles 2 rows; grid 512 = single wave.
// ---------------------------------------------------------------------------
__global__ void __launch_bounds__(256, 4)
spmm_t2(float4* __restrict__ out) {
    __shared__ int2 s_wd[16 * DEGREE];

    int tid = threadIdx.x;
    int wr  = tid >> 5;
    int c   = tid & 31;

    s_wd[tid]       = g_wdh[blockIdx.x * 512 + tid];
    s_wd[tid + 256] = g_wdh[blockIdx.x * 512 + tid + 256];
    __syncthreads();

    #pragma unroll
    for (int rb = 0; rb < 2; rb++) {
        int lrow = wr * 2 + rb;
        int row  = blockIdx.x * 16 + lrow;
        const int2* swd = &s_wd[lrow * DEGREE];
        const char* __restrict__ base = (const char*)g_h0 + c * 16;

        __half2 z = __floats2half2_rn(0.f, 0.f);
        __half2 A[4][4];
        #pragma unroll
        for (int q = 0; q < 4; q++)
            #pragma unroll
            for (int pp = 0; pp < 4; pp++) A[q][pp] = z;

        #pragma unroll
        for (int k = 0; k < DEGREE; k += 4) {
            int2 wd0 = swd[k + 0];
            int2 wd1 = swd[k + 1];
            int2 wd2 = swd[k + 2];
            int2 wd3 = swd[k + 3];
            uint4 v0 = *reinterpret_cast<const uint4*>(base + wd0.x);
            uint4 v1 = *reinterpret_cast<const uint4*>(base + wd1.x);
            uint4 v2 = *reinterpret_cast<const uint4*>(base + wd2.x);
            uint4 v3 = *reinterpret_cast<const uint4*>(base + wd3.x);
            __half2 w0 = *reinterpret_cast<__half2*>(&wd0.y);
            __half2 w1 = *reinterpret_cast<__half2*>(&wd1.y);
            __half2 w2 = *reinterpret_cast<__half2*>(&wd2.y);
            __half2 w3 = *reinterpret_cast<__half2*>(&wd3.y);
            const __half2* b0 = reinterpret_cast<const __half2*>(&v0);
            const __half2* b1 = reinterpret_cast<const __half2*>(&v1);
            const __half2* b2 = reinterpret_cast<const __half2*>(&v2);
            const __half2* b3 = reinterpret_cast<const __half2*>(&v3);
            #pragma unroll
            for (int pp = 0; pp < 4; pp++) {
                A[0][pp] = __hfma2(w0, b0[pp], A[0][pp]);
                A[1][pp] = __hfma2(w1, b1[pp], A[1][pp]);
                A[2][pp] = __hfma2(w2, b2[pp], A[2][pp]);
                A[3][pp] = __hfma2(w3, b3[pp], A[3][pp]);
            }
        }

        __half2 res[4];
        #pragma unroll
        for (int pp = 0; pp < 4; pp++)
            res[pp] = __hadd2(__hadd2(A[0][pp], A[1][pp]),
                              __hadd2(A[2][pp], A[3][pp]));

        // fp8 store of 32*x2 for the fp8 chain
        __half2 s32 = __floats2half2_rn(32.f, 32.f);
        __half2 q0 = __hmul2(res[0], s32);
        __half2 q1 = __hmul2(res[1], s32);
        __half2 q2 = __hmul2(res[2], s32);
        __half2 q3 = __hmul2(res[3], s32);
        g_f0[row * 32 + c] = make_uint2(pack_e4m3(q0, q1), pack_e4m3(q2, q3));

        // tap 2 (fp32 accumulate into out)
        float2 f0 = __half22float2(res[0]);
        float2 f1 = __half22float2(res[1]);
        float2 f2 = __half22float2(res[2]);
        float2 f3 = __half22float2(res[3]);
        int ob = row * D4 + c * 2;
        float4 a0 = out[ob];
        float4 a1 = out[ob + 1];
        a0.x += f0.x;  a0.y += f0.y;  a0.z += f1.x;  a0.w += f1.y;
        a1.x += f2.x;  a1.y += f2.y;  a1.z += f3.x;  a1.w += f3.y;
        out[ob]     = a0;
        out[ob + 1] = a1;
    }
}

// ---------------------------------------------------------------------------
// fp8 step (t=3..32): warp handles 2 rows; 32 lanes x 8B = 256B row.
// Buffers hold 32*x in e4m3; acc = sum w*v = 32*x_next (fp16 HFMA2, 2
// chains), re-stored directly. Grid 512 = single wave.
//   t=4,8,16: store acc (=32*x_t) to fp16 tap buffers
//   t=32:     final combine: out += t4/64 + t8/192 + t16/768 + acc/3840
// Parity: t=2 wrote g_f0; read = (t&1) ? g_f0 : g_f1.
// ---------------------------------------------------------------------------
__global__ void __launch_bounds__(256, 4)
spmm_f8(int t, float4* __restrict__ out) {
    __shared__ int2 s_wd[16 * DEGREE];

    const uint2* __restrict__ xin  = (t & 1) ? g_f0 : g_f1;
    uint2*       __restrict__ xout = (t & 1) ? g_f1 : g_f0;

    int tid = threadIdx.x;
    int wr  = tid >> 5;
    int c   = tid & 31;

    s_wd[tid]       = g_wdf[blockIdx.x * 512 + tid];
    s_wd[tid + 256] = g_wdf[blockIdx.x * 512 + tid + 256];
    __syncthreads();

    #pragma unroll
    for (int rb = 0; rb < 2; rb++) {
        int lrow = wr * 2 + rb;
        int row  = blockIdx.x * 16 + lrow;
        const int2* swd = &s_wd[lrow * DEGREE];

        const char* __restrict__ base = (const char*)xin + c * 8;

        __half2 z = __floats2half2_rn(0.f, 0.f);
        __half2 A[2][4];
        #pragma unroll
        for (int q = 0; q < 2; q++)
            #pragma unroll
            for (int pp = 0; pp < 4; pp++) A[q][pp] = z;

        #pragma unroll
        for (int k = 0; k < DEGREE; k += 8) {
            int2  wd[8];
            uint2 v[8];
            #pragma unroll
            for (int u = 0; u < 8; u++) wd[u] = swd[k + u];
            #pragma unroll
            for (int u = 0; u < 8; u++)
                v[u] = *reinterpret_cast<const uint2*>(base + wd[u].x);
            #pragma unroll
            for (int u = 0; u < 8; u++) {
                __half2 w2 = *reinterpret_cast<__half2*>(&wd[u].y);
                __half2 f0, f1, f2, f3;
                unpack_e4m3(v[u].x, f0, f1);
                unpack_e4m3(v[u].y, f2, f3);
                int q = u & 1;
                A[q][0] = __hfma2(w2, f0, A[q][0]);
                A[q][1] = __hfma2(w2, f1, A[q][1]);
                A[q][2] = __hfma2(w2, f2, A[q][2]);
                A[q][3] = __hfma2(w2, f3, A[q][3]);
            }
        }

        __half2 res[4];
        #pragma unroll
        for (int pp = 0; pp < 4; pp++) res[pp] = __hadd2(A[0][pp], A[1][pp]);

        if (t != 32)
            xout[row * 32 + c] = make_uint2(pack_e4m3(res[0], res[1]),
                                            pack_e4m3(res[2], res[3]));

        if (t == 4 || t == 8 || t == 16) {
            uint4 tv;
            tv.x = *reinterpret_cast<unsigned*>(&res[0]);
            tv.y = *reinterpret_cast<unsigned*>(&res[1]);
            tv.z = *reinterpret_cast<unsigned*>(&res[2]);
            tv.w = *reinterpret_cast<unsigned*>(&res[3]);
            if      (t == 4) g_t4 [row * 32 + c] = tv;
            else if (t == 8) g_t8 [row * 32 + c] = tv;
            else             g_t16[row * 32 + c] = tv;
        } else if (t == 32) {
            // final combine; out currently holds x1 + x2.
            // buffers hold 32*x -> coefficients: (1/2)/32, (1/6)/32, ...
            uint4 t4v  = g_t4 [row * 32 + c];
            uint4 t8v  = g_t8 [row * 32 + c];
            uint4 t16v = g_t16[row * 32 + c];
            const __half2* h4  = reinterpret_cast<const __half2*>(&t4v);
            const __half2* h8  = reinterpret_cast<const __half2*>(&t8v);
            const __half2* h16 = reinterpret_cast<const __half2*>(&t16v);

            float fs[8];
            #pragma unroll
            for (int pp = 0; pp < 4; pp++) {
                float2 a4  = __half22float2(h4[pp]);
                float2 a8  = __half22float2(h8[pp]);
                float2 a16 = __half22float2(h16[pp]);
                float2 a32 = __half22float2(res[pp]);
                fs[pp*2]   = a4.x*(1.f/64.f)  + a8.x*(1.f/192.f)
                           + a16.x*(1.f/768.f) + a32.x*(1.f/3840.f);
                fs[pp*2+1] = a4.y*(1.f/64.f)  + a8.y*(1.f/192.f)
                           + a16.y*(1.f/768.f) + a32.y*(1.f/3840.f);
            }
            int ob = row * D4 + c * 2;
            float4 a0 = out[ob];
            float4 a1 = out[ob + 1];
            a0.x += fs[0];  a0.y += fs[1];  a0.z += fs[2];  a0.w += fs[3];
            a1.x += fs[4];  a1.y += fs[5];  a1.z += fs[6];  a1.w += fs[7];
            out[ob]     = a0;
            out[ob + 1] = a1;
        }
    }
}

// ---------------------------------------------------------------------------
// inputs (metadata order): src(int), dst(int), e(float32), h(float32)
// output: float32 [N_NODES, D_FEAT]
//
// out = A h + (A^2 h)/1! + (A^4 h)/2! + (A^8 h)/3! + (A^16 h)/4! + (A^32 h)/5!
// via 32 sparse applications: t=1 fp16-gather/fp32-accum, t=2 fp16,
// t=3..32 e4m3 (scaled 32) with fp16 accumulation. Taps 1,2 fp32 into out;
// taps 4,8,16 via fp16 side buffers folded into the final t=32 combine.
// ---------------------------------------------------------------------------
extern "C" void kernel_launch(void* const* d_in, const int* in_sizes, int n_in,
                              void* d_out, int out_size) {
    const void*   dst = d_in[1];
    const float*  e   = (const float*)d_in[2];
    const float4* h   = (const float4*)d_in[3];
    float4*       out = (float4*)d_out;

    prep_kernel<<<N_EDGES / 256, 256>>>(dst, e);
    cvt_h_kernel<<<512, 256>>>(h);

    spmm_t1<<<N_NODES / 16, 256>>>(out);
    spmm_t2<<<N_NODES / 16, 256>>>(out);

    for (int t = 3; t <= 32; t++)
        spmm_f8<<<N_NODES / 16, 256>>>(t, out);
}